// round 1
// baseline (speedup 1.0000x reference)
#include <cuda_runtime.h>

#define NFFT    1024
#define THREADS 256
// Skewed shared addressing: kills the 32-way conflict of the bit-reversal
// scatter (low 5 bits of rev(i) are warp-constant -> 33*L + c is a bank bijection)
#define SKEW(i) ((i) + ((i) >> 5))

__global__ __launch_bounds__(THREADS)
void ifft1024_kernel(const float* __restrict__ xre,
                     const float* __restrict__ xim,
                     float* __restrict__ ore,
                     float* __restrict__ oim)
{
    __shared__ float sr[NFFT + NFFT / 32];
    __shared__ float si[NFFT + NFFT / 32];
    __shared__ float twr[512 + 16];
    __shared__ float twi[512 + 16];

    const int t = threadIdx.x;
    const size_t base = (size_t)blockIdx.x * NFFT;

    // Twiddle table: w^k = exp(+2*pi*i*k/1024)  (inverse-transform sign), k in [0,512)
    // Precise sincosf = polynomial on the (otherwise idle) FMA pipe; only 2/thread.
    #pragma unroll
    for (int u = 0; u < 2; u++) {
        int k = t + u * THREADS;
        float s, c;
        sincosf(6.283185307179586476925e0f * (float)k * (1.0f / (float)NFFT), &s, &c);
        twr[SKEW(k)] = c;
        twi[SKEW(k)] = s;
    }

    // Coalesced global load, bit-reversed scatter into (skewed) shared.
    const float scale = 1.0f / (float)NFFT;   // ifft normalization (1/128 * 1/8)
    #pragma unroll
    for (int u = 0; u < 4; u++) {
        int i = t + u * THREADS;
        int r = __brev((unsigned)i) >> 22;    // 10-bit bit reversal
        float vr = xre[base + i] * scale;
        float vi = xim[base + i] * scale;
        sr[SKEW(r)] = vr;
        si[SKEW(r)] = vi;
    }
    __syncthreads();

    // 10 radix-2 DIT stages. 512 butterflies/stage, 2 per thread.
    // Butterflies within a stage touch disjoint index pairs -> no intra-stage hazard.
    #pragma unroll
    for (int s = 0; s < 10; s++) {
        #pragma unroll
        for (int u = 0; u < 2; u++) {
            int j    = t + u * THREADS;
            int half = 1 << s;
            int pos  = j & (half - 1);
            int i0   = ((j >> s) << (s + 1)) | pos;
            int i1   = i0 + half;
            int ti   = pos << (9 - s);

            float wr = twr[SKEW(ti)];
            float wi = twi[SKEW(ti)];

            float br = sr[SKEW(i1)];
            float bi = si[SKEW(i1)];
            float tr = fmaf(br, wr, -bi * wi);
            float tq = fmaf(br, wi,  bi * wr);

            float ar = sr[SKEW(i0)];
            float ai = si[SKEW(i0)];

            sr[SKEW(i0)] = ar + tr;
            si[SKEW(i0)] = ai + tq;
            sr[SKEW(i1)] = ar - tr;
            si[SKEW(i1)] = ai - tq;
        }
        __syncthreads();
    }

    // Natural-order coalesced store.
    #pragma unroll
    for (int u = 0; u < 4; u++) {
        int i = t + u * THREADS;
        ore[base + i] = sr[SKEW(i)];
        oim[base + i] = si[SKEW(i)];
    }
}

extern "C" void kernel_launch(void* const* d_in, const int* in_sizes, int n_in,
                              void* d_out, int out_size)
{
    const float* re = (const float*)d_in[0];
    const float* im = (const float*)d_in[1];
    float* out = (float*)d_out;

    const int n_elems = in_sizes[0];      // 8*4096*1024 = 33554432
    const int rows    = n_elems / NFFT;   // 32768

    float* ore = out;                     // output tuple: [re | im]
    float* oim = out + (size_t)n_elems;

    ifft1024_kernel<<<rows, THREADS>>>(re, im, ore, oim);
}

// round 2
// speedup vs baseline: 1.7129x; 1.7129x over previous
#include <cuda_runtime.h>

#define NFFT    1024
#define THREADS 256
// Skew kills stride-32-multiple bank conflicts (bit-rev scatter, strided rounds)
#define SK(i) ((i) + ((i) >> 5))

__global__ __launch_bounds__(THREADS)
void ifft1024_r4(const float4* __restrict__ xre4,
                 const float4* __restrict__ xim4,
                 float* __restrict__ ore,
                 float* __restrict__ oim)
{
    __shared__ float sr[NFFT + NFFT / 32];
    __shared__ float si[NFFT + NFFT / 32];

    const int t = threadIdx.x;
    const size_t row = (size_t)blockIdx.x;
    const float scale = 1.0f / (float)NFFT;

    // ---- Coalesced vector load + bit-reversed scatter into skewed shared ----
    float4 vr = xre4[row * (NFFT / 4) + t];
    float4 vi = xim4[row * (NFFT / 4) + t];
    {
        const int gi = t << 2;
        int r0 = __brev((unsigned)(gi + 0)) >> 22;
        int r1 = __brev((unsigned)(gi + 1)) >> 22;
        int r2 = __brev((unsigned)(gi + 2)) >> 22;
        int r3 = __brev((unsigned)(gi + 3)) >> 22;
        sr[SK(r0)] = vr.x * scale;  si[SK(r0)] = vi.x * scale;
        sr[SK(r1)] = vr.y * scale;  si[SK(r1)] = vi.y * scale;
        sr[SK(r2)] = vr.z * scale;  si[SK(r2)] = vi.z * scale;
        sr[SK(r3)] = vr.w * scale;  si[SK(r3)] = vi.w * scale;
    }
    __syncthreads();

    // ---- 5 radix-4 rounds (each = two fused radix-2 stages in registers) ----
    // Round u: h = 4^u. Thread owns indices i0 + k*h, k=0..3 (disjoint groups),
    // so no sync needed between the read and write of the same round.
    float z0r, z0i, z1r, z1i, z2r, z2i, z3r, z3i;

    #pragma unroll
    for (int u = 0; u < 5; u++) {
        const int h   = 1 << (2 * u);
        const int pos = t & (h - 1);
        const int i0  = ((t >> (2 * u)) << (2 * u + 2)) | pos;

        const float x0r = sr[SK(i0)],         x0i = si[SK(i0)];
        const float x1r = sr[SK(i0 + h)],     x1i = si[SK(i0 + h)];
        const float x2r = sr[SK(i0 + 2 * h)], x2i = si[SK(i0 + 2 * h)];
        const float x3r = sr[SK(i0 + 3 * h)], x3i = si[SK(i0 + 3 * h)];

        // Twiddles (inverse sign): wB = exp(+2*pi*i * pos / (4h)), wA = wB^2
        float wAr, wAi, wBr, wBi;
        if (u == 0) {
            wAr = 1.0f; wAi = 0.0f; wBr = 1.0f; wBi = 0.0f;
        } else {
            const float ang = (float)pos * (6.283185307179586f / (float)(4 * h));
            __sincosf(ang, &wBi, &wBr);           // angle in [0, pi/2)
            wAr = wBr * wBr - wBi * wBi;
            wAi = 2.0f * wBr * wBi;
        }

        // Stage A (radix-2, distance h): pairs (x0,x1), (x2,x3), twiddle wA
        float tr, ti;
        tr = x1r * wAr - x1i * wAi;  ti = x1r * wAi + x1i * wAr;
        const float b0r = x0r + tr, b0i = x0i + ti;
        const float b1r = x0r - tr, b1i = x0i - ti;
        tr = x3r * wAr - x3i * wAi;  ti = x3r * wAi + x3i * wAr;
        const float b2r = x2r + tr, b2i = x2i + ti;
        const float b3r = x2r - tr, b3i = x2i - ti;

        // Stage B (radix-2, distance 2h): (b0,b2) twiddle wB, (b1,b3) twiddle i*wB
        tr = b2r * wBr - b2i * wBi;  ti = b2r * wBi + b2i * wBr;
        z0r = b0r + tr;  z0i = b0i + ti;
        z2r = b0r - tr;  z2i = b0i - ti;
        // i*wB = (-wBi, wBr)
        tr = -(b3r * wBi) - b3i * wBr;  ti = b3r * wBr - b3i * wBi;
        z1r = b1r + tr;  z1i = b1i + ti;
        z3r = b1r - tr;  z3i = b1i - ti;

        if (u < 4) {
            sr[SK(i0)]         = z0r;  si[SK(i0)]         = z0i;
            sr[SK(i0 + h)]     = z1r;  si[SK(i0 + h)]     = z1i;
            sr[SK(i0 + 2 * h)] = z2r;  si[SK(i0 + 2 * h)] = z2i;
            sr[SK(i0 + 3 * h)] = z3r;  si[SK(i0 + 3 * h)] = z3i;
            __syncthreads();
        }
    }

    // ---- Round 4 outputs are at t + 256k: store straight to global, coalesced ----
    const size_t ob = row * NFFT + t;
    ore[ob +   0] = z0r;  oim[ob +   0] = z0i;
    ore[ob + 256] = z1r;  oim[ob + 256] = z1i;
    ore[ob + 512] = z2r;  oim[ob + 512] = z2i;
    ore[ob + 768] = z3r;  oim[ob + 768] = z3i;
}

extern "C" void kernel_launch(void* const* d_in, const int* in_sizes, int n_in,
                              void* d_out, int out_size)
{
    const float4* re4 = (const float4*)d_in[0];
    const float4* im4 = (const float4*)d_in[1];
    float* out = (float*)d_out;

    const int n_elems = in_sizes[0];      // 8*4096*1024
    const int rows    = n_elems / NFFT;   // 32768

    float* ore = out;
    float* oim = out + (size_t)n_elems;

    ifft1024_r4<<<rows, THREADS>>>(re4, im4, ore, oim);
}

// round 3
// speedup vs baseline: 2.5970x; 1.5161x over previous
#include <cuda_runtime.h>

#define NFFT 1024
#define T_PER_BLK 128

// XOR bank swizzle: fold addr bits [6:8) into bank bits [3:5).
// Bijection on [0,1024); keeps runs of <=8 contiguous floats contiguous.
__device__ __forceinline__ int SWZ(int a) { return a ^ ((a >> 3) & 24); }

// In-place inverse DFT-8 (twiddle sign +i). Inputs x[c], outputs X[c'].
__device__ __forceinline__ void radix8_inv(float* r, float* i)
{
    const float RQ = 0.7071067811865476f;
    // evens (x0,x2,x4,x6)
    float e0r = r[0] + r[4], e0i = i[0] + i[4];
    float e1r = r[0] - r[4], e1i = i[0] - i[4];
    float e2r = r[2] + r[6], e2i = i[2] + i[6];
    float e3r = r[2] - r[6], e3i = i[2] - i[6];
    float E0r = e0r + e2r, E0i = e0i + e2i;
    float E2r = e0r - e2r, E2i = e0i - e2i;
    float E1r = e1r - e3i, E1i = e1i + e3r;   // e1 + i*e3
    float E3r = e1r + e3i, E3i = e1i - e3r;   // e1 - i*e3
    // odds (x1,x3,x5,x7)
    float o0r = r[1] + r[5], o0i = i[1] + i[5];
    float o1r = r[1] - r[5], o1i = i[1] - i[5];
    float o2r = r[3] + r[7], o2i = i[3] + i[7];
    float o3r = r[3] - r[7], o3i = i[3] - i[7];
    float O0r = o0r + o2r, O0i = o0i + o2i;
    float O2r = o0r - o2r, O2i = o0i - o2i;
    float O1r = o1r - o3i, O1i = o1i + o3r;
    float O3r = o1r + o3i, O3i = o1i - o3r;
    // odd twiddles: w1 = RQ(1+i), w2 = i, w3 = RQ(-1+i)
    float T1r = RQ * (O1r - O1i), T1i = RQ * (O1r + O1i);
    float T2r = -O2i,             T2i = O2r;
    float T3r = -RQ * (O3r + O3i), T3i = RQ * (O3r - O3i);

    r[0] = E0r + O0r; i[0] = E0i + O0i;
    r[4] = E0r - O0r; i[4] = E0i - O0i;
    r[1] = E1r + T1r; i[1] = E1i + T1i;
    r[5] = E1r - T1r; i[5] = E1i - T1i;
    r[2] = E2r + T2r; i[2] = E2i + T2i;
    r[6] = E2r - T2r; i[6] = E2i - T2i;
    r[3] = E3r + T3r; i[3] = E3i + T3i;
    r[7] = E3r - T3r; i[7] = E3i - T3i;
}

// Apply x[c] *= w^c for c=1..7 via power chaining (1 sincos upstream).
__device__ __forceinline__ void twiddle_chain(float* xr, float* xi,
                                              float wr, float wi)
{
    float cwr = wr, cwi = wi;
    #pragma unroll
    for (int c = 1; c < 8; c++) {
        float tr = xr[c] * cwr - xi[c] * cwi;
        xi[c]    = xr[c] * cwi + xi[c] * cwr;
        xr[c]    = tr;
        if (c < 7) {
            float nr = cwr * wr - cwi * wi;
            cwi      = cwr * wi + cwi * wr;
            cwr      = nr;
        }
    }
}

__global__ __launch_bounds__(T_PER_BLK)
void ifft1024_stockham(const float* __restrict__ xre,
                       const float* __restrict__ xim,
                       float* __restrict__ ore,
                       float* __restrict__ oim)
{
    __shared__ float s_r[2][NFFT];
    __shared__ float s_i[2][NFFT];

    const int t = threadIdx.x;                 // 0..127
    const size_t base = (size_t)blockIdx.x * NFFT;
    const float scale = 1.0f / (float)NFFT;
    const float TWO_PI = 6.283185307179586f;

    float xr[8], xi[8];

    // ================= stage 0: radix-8, M=1 (no twiddle) =================
    // Reads global at t + 128c (coalesced), writes 8 contiguous at 8t.
    #pragma unroll
    for (int c = 0; c < 8; c++) {
        xr[c] = xre[base + t + 128 * c] * scale;
        xi[c] = xim[base + t + 128 * c] * scale;
    }
    radix8_inv(xr, xi);
    {
        int b = SWZ(8 * t);   // swizzle constant across the 8-float run
        *(float4*)&s_r[0][b]     = make_float4(xr[0], xr[1], xr[2], xr[3]);
        *(float4*)&s_r[0][b + 4] = make_float4(xr[4], xr[5], xr[6], xr[7]);
        *(float4*)&s_i[0][b]     = make_float4(xi[0], xi[1], xi[2], xi[3]);
        *(float4*)&s_i[0][b + 4] = make_float4(xi[4], xi[5], xi[6], xi[7]);
    }
    __syncthreads();

    // ================= stage 1: radix-8, M=8 =================
    {
        #pragma unroll
        for (int c = 0; c < 8; c++) {
            int a = SWZ(t + 128 * c);
            xr[c] = s_r[0][a];
            xi[c] = s_i[0][a];
        }
        int tm = t & 7;
        float wr, wi;
        __sincosf(TWO_PI * (float)tm * (1.0f / 64.0f), &wi, &wr);
        twiddle_chain(xr, xi, wr, wi);
        radix8_inv(xr, xi);
        int wb = tm + ((t >> 3) << 6);         // t%8 + 64*(t/8)
        #pragma unroll
        for (int c = 0; c < 8; c++) {
            int a = SWZ(wb + 8 * c);
            s_r[1][a] = xr[c];
            s_i[1][a] = xi[c];
        }
    }
    __syncthreads();

    // ================= stage 2: radix-8, M=64 =================
    {
        #pragma unroll
        for (int c = 0; c < 8; c++) {
            int a = SWZ(t + 128 * c);
            xr[c] = s_r[1][a];
            xi[c] = s_i[1][a];
        }
        int tm = t & 63;
        float wr, wi;
        __sincosf(TWO_PI * (float)tm * (1.0f / 512.0f), &wi, &wr);
        twiddle_chain(xr, xi, wr, wi);
        radix8_inv(xr, xi);
        int wb = tm + ((t >> 6) << 9);         // t%64 + 512*(t/64)
        #pragma unroll
        for (int c = 0; c < 8; c++) {
            int a = SWZ(wb + 64 * c);
            s_r[0][a] = xr[c];
            s_i[0][a] = xi[c];
        }
    }
    __syncthreads();

    // ================= stage 3: radix-2, M=512, write global =================
    {
        const int T4 = 4 * t;
        int a0 = SWZ(T4);
        int a1 = SWZ(T4 + 512);
        float4 ar = *(const float4*)&s_r[0][a0];
        float4 ai = *(const float4*)&s_i[0][a0];
        float4 br = *(const float4*)&s_r[0][a1];
        float4 bi = *(const float4*)&s_i[0][a1];

        // w_k = exp(+2*pi*i*(4t+k)/1024), chained from k=0
        float wr, wi;
        __sincosf(TWO_PI * (float)T4 * (1.0f / 1024.0f), &wi, &wr);
        const float str = 0.9999811752826011f;   // cos(2*pi/1024)
        const float sti = 0.006135884649154475f; // sin(2*pi/1024)

        float pr[4], pi_[4], qr[4], qi[4];
        float arr[4] = {ar.x, ar.y, ar.z, ar.w};
        float aii[4] = {ai.x, ai.y, ai.z, ai.w};
        float brr[4] = {br.x, br.y, br.z, br.w};
        float bii[4] = {bi.x, bi.y, bi.z, bi.w};
        #pragma unroll
        for (int k = 0; k < 4; k++) {
            float tr = brr[k] * wr - bii[k] * wi;
            float ti = brr[k] * wi + bii[k] * wr;
            pr[k]  = arr[k] + tr;  pi_[k] = aii[k] + ti;
            qr[k]  = arr[k] - tr;  qi[k]  = aii[k] - ti;
            if (k < 3) {
                float nr = wr * str - wi * sti;
                wi       = wr * sti + wi * str;
                wr       = nr;
            }
        }
        *(float4*)&ore[base + T4]       = make_float4(pr[0], pr[1], pr[2], pr[3]);
        *(float4*)&oim[base + T4]       = make_float4(pi_[0], pi_[1], pi_[2], pi_[3]);
        *(float4*)&ore[base + T4 + 512] = make_float4(qr[0], qr[1], qr[2], qr[3]);
        *(float4*)&oim[base + T4 + 512] = make_float4(qi[0], qi[1], qi[2], qi[3]);
    }
}

extern "C" void kernel_launch(void* const* d_in, const int* in_sizes, int n_in,
                              void* d_out, int out_size)
{
    const float* re = (const float*)d_in[0];
    const float* im = (const float*)d_in[1];
    float* out = (float*)d_out;

    const int n_elems = in_sizes[0];      // 8*4096*1024
    const int rows    = n_elems / NFFT;   // 32768

    float* ore = out;
    float* oim = out + (size_t)n_elems;

    ifft1024_stockham<<<rows, T_PER_BLK>>>(re, im, ore, oim);
}